// round 4
// baseline (speedup 1.0000x reference)
#include <cuda_runtime.h>
#include <cuda_bf16.h>
#include <math.h>

#define BB      32
#define TT      64
#define NEV     2048      // B*T events
#define NOCC    4096      // 2*B*T occurrences
#define DIMD    128
#define DIMC    64
#define DIML    256
#define FEAT    320
#define INDIM   449
#define ES      452       // padded e row stride
#define NH      4
#define DH      80
#define NWAVES  12
#define OUT_FULL 25802049  // 1 + 2048 + 200000*128 + 200000

// ------------------------ device scratch ------------------------------------
__device__ int   g_prevRead[NOCC];
__device__ int   g_isLast[NOCC];
__device__ int   g_depth[NEV];
__device__ float g_dts[NEV];
__device__ float g_dto[NEV];
__device__ float g_newS[NEV * DIMD];
__device__ float g_newO[NEV * DIMD];
__device__ float g_x[NEV * FEAT];
__device__ float g_e[NEV * ES + 64];     // +64 pad: last-tile float4 overread
__device__ float g_q[NEV * FEAT];
__device__ float g_k[NEV * FEAT];
__device__ float g_v[NEV * FEAT];
__device__ float g_ao[NEV * FEAT];
__device__ float g_s1[NEV * DIMD];
__device__ float g_loss[NEV];

__device__ __forceinline__ float sigm(float x) { return 1.f / (1.f + expf(-x)); }

// ------------------------ kernel A1: occurrence links -----------------------
// occurrence pos = t*64 + phase*32 + b   (phase 0 = subject write, 1 = object)
__global__ void links_kernel(const int* __restrict__ subj, const int* __restrict__ obj,
                             const float* __restrict__ tim, const float* __restrict__ lt)
{
    __shared__ int s_ent[NOCC];
    int tid = threadIdx.x;
    for (int p = tid; p < NOCC; p += 256) {
        int t = p >> 6, r = p & 63, ph = r >> 5, b = r & 31;
        s_ent[p] = ph ? obj[b * TT + t] : subj[b * TT + t];
    }
    __syncthreads();
    int pos = blockIdx.x * 256 + tid;
    int e = s_ent[pos];
    int t = pos >> 6, r = pos & 63, ph = r >> 5, b = r & 31;
    int stepStart = t * 64;
    int prevR = -1, later = 0;
    for (int p2 = 0; p2 < NOCC; p2++) {
        if (s_ent[p2] == e) {
            if (p2 < stepStart) prevR = p2;   // last writer before this step
            if (p2 > pos) later = 1;
        }
    }
    g_prevRead[pos] = prevR;
    g_isLast[pos] = !later;
    float ltv = (prevR < 0) ? lt[e] : tim[(prevR & 31) * TT + (prevR >> 6)];
    float dt = tim[b * TT + t] - ltv;
    int ev = t * 32 + b;
    if (ph == 0) g_dts[ev] = dt; else g_dto[ev] = dt;
}

// ------------------------ kernel A2: event depths ----------------------------
__global__ void depth_kernel()
{
    __shared__ int s_d[NEV];
    __shared__ int s_ps[NEV];
    __shared__ int s_po[NEV];
    int tid = threadIdx.x;
    for (int ev = tid; ev < NEV; ev += 256) {
        int t = ev >> 5, b = ev & 31;
        int ps = g_prevRead[t * 64 + b];
        int po = g_prevRead[t * 64 + 32 + b];
        s_ps[ev] = (ps < 0) ? -1 : ((ps >> 6) * 32 + (ps & 31));
        s_po[ev] = (po < 0) ? -1 : ((po >> 6) * 32 + (po & 31));
        s_d[ev] = -1;
    }
    __syncthreads();
    for (int pass = 0; pass < 32; pass++) {
        for (int ev = tid; ev < NEV; ev += 256) {
            if (s_d[ev] < 0) {
                int a = s_ps[ev], b2 = s_po[ev];
                int da = (a < 0) ? -1 : s_d[a];
                int db = (b2 < 0) ? -1 : s_d[b2];
                bool ra = (a < 0) || (da >= 0);
                bool rb = (b2 < 0) || (db >= 0);
                if (ra && rb) s_d[ev] = max(da, db) + 1;
            }
        }
        __syncthreads();
    }
    for (int ev = tid; ev < NEV; ev += 256) g_depth[ev] = s_d[ev];
}

// ------------------------ kernel B: one dependency wave ----------------------
#define SI 321
#define SH 257
__global__ void __launch_bounds__(256) wave_kernel(
    int w,
    const int* __restrict__ subj, const int* __restrict__ obj,
    const int* __restrict__ rel,
    const float* __restrict__ mem, const float* __restrict__ remb,
    const float* __restrict__ Wh, const float* __restrict__ Whh,
    const float* __restrict__ Wst, const float* __restrict__ Wot)
{
    __shared__ float s_inp[16 * SI];
    __shared__ float s_h[16 * SH];
    __shared__ int   s_act[16];
    __shared__ int   s_any;
    int tid = threadIdx.x;
    int ev0 = blockIdx.x * 16;
    if (tid < 16) s_act[tid] = (g_depth[ev0 + tid] == w);
    if (tid == 0) s_any = 0;
    __syncthreads();
    if (tid < 16 && s_act[tid]) atomicOr(&s_any, 1);
    __syncthreads();
    if (!s_any) return;

    // gather inp = [s_emb | o_emb | r_emb] for 16 events
    for (int idx = tid; idx < 16 * FEAT; idx += 256) {
        int rrow = idx / FEAT, f = idx - rrow * FEAT;
        int ev = ev0 + rrow;
        int t = ev >> 5, b = ev & 31;
        float val;
        if (f < 256) {
            int which = f >> 7, ff = f & 127;
            int pos = t * 64 + which * 32 + b;
            int pred = g_prevRead[pos];
            if (pred < 0) {
                int ent = which ? obj[b * TT + t] : subj[b * TT + t];
                val = mem[(size_t)ent * DIMD + ff];
            } else {
                int pph = (pred >> 5) & 1;
                int pev = (pred >> 6) * 32 + (pred & 31);
                val = pph ? g_newO[pev * DIMD + ff] : g_newS[pev * DIMD + ff];
            }
        } else {
            val = remb[rel[b * TT + t] * DIMC + (f - 256)];
        }
        s_inp[rrow * SI + f] = val;
    }
    __syncthreads();

    // h = sigmoid(inp @ W_hidden)  [16,320]@[320,256]
    {
        int cg = tid & 63;      // col group (4 cols)
        int rg = tid >> 6;      // row group (4 rows)
        float acc[4][4];
        #pragma unroll
        for (int r = 0; r < 4; r++)
            #pragma unroll
            for (int c = 0; c < 4; c++) acc[r][c] = 0.f;
        for (int k = 0; k < FEAT; k++) {
            float4 wv = *(const float4*)(Wh + (size_t)k * DIML + cg * 4);
            #pragma unroll
            for (int r = 0; r < 4; r++) {
                float a = s_inp[(rg * 4 + r) * SI + k];
                acc[r][0] += a * wv.x; acc[r][1] += a * wv.y;
                acc[r][2] += a * wv.z; acc[r][3] += a * wv.w;
            }
        }
        #pragma unroll
        for (int r = 0; r < 4; r++)
            #pragma unroll
            for (int c = 0; c < 4; c++)
                s_h[(rg * 4 + r) * SH + cg * 4 + c] = sigm(acc[r][c]);
    }
    __syncthreads();

    // hh = h @ W_hh  [16,256]@[256,128]; then new_s/new_o
    {
        int j = tid & 127;
        int half = tid >> 7;    // 8 rows each
        float acc2[8];
        #pragma unroll
        for (int r = 0; r < 8; r++) acc2[r] = 0.f;
        for (int k = 0; k < DIML; k++) {
            float wv = Whh[(size_t)k * DIMD + j];
            #pragma unroll
            for (int r = 0; r < 8; r++)
                acc2[r] += s_h[(half * 8 + r) * SH + k] * wv;
        }
        float wst = Wst[j], wot = Wot[j];
        #pragma unroll
        for (int r = 0; r < 8; r++) {
            int rrow = half * 8 + r;
            if (s_act[rrow]) {
                int ev = ev0 + rrow;
                g_newS[ev * DIMD + j] = sigm(g_dts[ev] * wst + acc2[r]);
                g_newO[ev * DIMD + j] = sigm(g_dto[ev] * wot + acc2[r]);
            }
        }
    }
}

// ------------------------ kernel C: assemble evt rows ------------------------
__global__ void assemble_x_kernel(const int* __restrict__ rel,
                                  const float* __restrict__ remb)
{
    int idx = blockIdx.x * 256 + threadIdx.x;
    if (idx >= NEV * FEAT) return;
    int row = idx / FEAT, f = idx - row * FEAT;  // row = b*64 + t
    int b = row >> 6, t = row & 63;
    int ev = t * 32 + b;
    float val;
    if (f < 128)      val = g_newS[ev * DIMD + f];
    else if (f < 256) val = g_newO[ev * DIMD + (f - 128)];
    else              val = remb[rel[row] * DIMC + (f - 256)];
    g_x[idx] = val;
}

// ------------------------ build e = [x | time_emb | 1 | pad] -----------------
__global__ void build_e_kernel(const float* __restrict__ tim)
{
    int idx = blockIdx.x * 256 + threadIdx.x;
    if (idx >= NEV * ES) return;
    int row = idx / ES, f = idx - row * ES;
    float val;
    if (f < FEAT) val = g_x[row * FEAT + f];
    else if (f < FEAT + DIMD) {
        int d = f - FEAT;
        // norm = 1/(10000^d) computed as fp32 like the reference (inf -> 0)
        float p = powf(10000.0f, (float)d);
        float nrm = (isinf(p)) ? 0.0f : (1.0f / p);
        val = sinf(tim[row] * nrm);
    } else if (f == INDIM - 1) val = 1.0f;
    else val = 0.0f;
    g_e[idx] = val;
}

// ------------------------ generic tiled fp32 GEMM ----------------------------
// C[M,N] = A[M,K] @ B[K,N]; epi 0: store, 1: C += tanh(acc), 2: relu(acc+bias)
__global__ void __launch_bounds__(256) gemm_kernel(
    const float* __restrict__ A, int lda,
    const float* __restrict__ Bm, int ldb,
    float* __restrict__ C, int ldc,
    int M, int N, int K, int epi, const float* __restrict__ bias)
{
    __shared__ float As[16][68];
    __shared__ float Bs[16][68];
    int tid = threadIdx.x;
    int tx = tid & 15, ty = tid >> 4;
    int row0 = blockIdx.y * 64;
    int col0 = blockIdx.x * 64;
    float acc[4][4];
    #pragma unroll
    for (int r = 0; r < 4; r++)
        #pragma unroll
        for (int c = 0; c < 4; c++) acc[r][c] = 0.f;

    int am = tid >> 2;            // row for A loads (0..63)
    int ak = (tid & 3) * 4;       // k offset (0,4,8,12)
    int bn = (tid & 15) * 4;      // n offset for B loads
    int bk = tid >> 4;            // k index (0..15)

    for (int kt = 0; kt < K; kt += 16) {
        // A tile (A buffers padded so float4 in-bounds even on K tail)
        float4 av = *(const float4*)(A + (size_t)(row0 + am) * lda + kt + ak);
        As[ak + 0][am] = av.x; As[ak + 1][am] = av.y;
        As[ak + 2][am] = av.z; As[ak + 3][am] = av.w;
        // B tile (guard K; tail garbage in As is multiplied by these zeros)
        int gk = kt + bk;
        float4 bv = make_float4(0.f, 0.f, 0.f, 0.f);
        if (gk < K) bv = *(const float4*)(Bm + (size_t)gk * ldb + col0 + bn);
        *(float4*)&Bs[bk][bn] = bv;
        __syncthreads();
        #pragma unroll
        for (int kk = 0; kk < 16; kk++) {
            float4 a = *(const float4*)&As[kk][ty * 4];
            float4 b = *(const float4*)&Bs[kk][tx * 4];
            acc[0][0] += a.x * b.x; acc[0][1] += a.x * b.y; acc[0][2] += a.x * b.z; acc[0][3] += a.x * b.w;
            acc[1][0] += a.y * b.x; acc[1][1] += a.y * b.y; acc[1][2] += a.y * b.z; acc[1][3] += a.y * b.w;
            acc[2][0] += a.z * b.x; acc[2][1] += a.z * b.y; acc[2][2] += a.z * b.z; acc[2][3] += a.z * b.w;
            acc[3][0] += a.w * b.x; acc[3][1] += a.w * b.y; acc[3][2] += a.w * b.z; acc[3][3] += a.w * b.w;
        }
        __syncthreads();
    }
    #pragma unroll
    for (int r = 0; r < 4; r++) {
        int rr = row0 + ty * 4 + r;
        #pragma unroll
        for (int c = 0; c < 4; c++) {
            int cc = col0 + tx * 4 + c;
            float v = acc[r][c];
            if (epi == 1)      C[(size_t)rr * ldc + cc] += tanhf(v);
            else if (epi == 2) C[(size_t)rr * ldc + cc] = fmaxf(v + bias[cc], 0.f);
            else               C[(size_t)rr * ldc + cc] = v;
        }
    }
}

// ------------------------ attention (per b,h block) --------------------------
// dyn smem: sq[64*84], sk[64*84], sv[64*84], ssc[64*68]  = 81920 bytes
__global__ void __launch_bounds__(256) attn_kernel()
{
    extern __shared__ float sm[];
    float* sq = sm;
    float* sk = sq + 64 * 84;
    float* sv = sk + 64 * 84;
    float* ssc = sv + 64 * 84;
    int b = blockIdx.x, h = blockIdx.y;
    int tid = threadIdx.x;
    const float scale = 0.111803398875f;  // 1/sqrt(80)

    for (int idx = tid; idx < 64 * DH; idx += 256) {
        int i = idx / DH, d = idx - i * DH;
        int row = b * TT + i, col = h * DH + d;
        sq[i * 84 + d] = g_q[(size_t)row * FEAT + col];
        sk[i * 84 + d] = g_k[(size_t)row * FEAT + col];
        sv[i * 84 + d] = g_v[(size_t)row * FEAT + col];
    }
    __syncthreads();

    // scores
    {
        int i = tid >> 2, jg = tid & 3;
        float acc[16];
        #pragma unroll
        for (int jj = 0; jj < 16; jj++) acc[jj] = 0.f;
        for (int kk = 0; kk < 20; kk++) {
            float4 qv = *(const float4*)&sq[i * 84 + kk * 4];
            #pragma unroll
            for (int jj = 0; jj < 16; jj++) {
                int j = jg * 16 + jj;
                float4 kv = *(const float4*)&sk[j * 84 + kk * 4];
                acc[jj] += qv.x * kv.x + qv.y * kv.y + qv.z * kv.z + qv.w * kv.w;
            }
        }
        #pragma unroll
        for (int jj = 0; jj < 16; jj++)
            ssc[i * 68 + jg * 16 + jj] = acc[jj] * scale;
    }
    __syncthreads();

    // strict-causal masked softmax per row; row 0 -> zeros
    if (tid < 64) {
        int i = tid;
        if (i == 0) {
            for (int j = 0; j < 64; j++) ssc[j] = 0.f;
        } else {
            float mx = -1e30f;
            for (int j = 0; j < i; j++) mx = fmaxf(mx, ssc[i * 68 + j]);
            float sum = 0.f;
            for (int j = 0; j < i; j++) sum += expf(ssc[i * 68 + j] - mx);
            float inv = 1.f / sum;
            for (int j = 0; j < i; j++) ssc[i * 68 + j] = expf(ssc[i * 68 + j] - mx) * inv;
            for (int j = i; j < 64; j++) ssc[i * 68 + j] = 0.f;
        }
    }
    __syncthreads();

    // out = attn @ v
    {
        int i = tid >> 2, dg = tid & 3, d0 = dg * 20;
        float acc[20];
        #pragma unroll
        for (int dd = 0; dd < 20; dd++) acc[dd] = 0.f;
        for (int j = 0; j < 64; j++) {
            float a = ssc[i * 68 + j];
            #pragma unroll
            for (int dd = 0; dd < 20; dd++)
                acc[dd] += a * sv[j * 84 + d0 + dd];
        }
        int row = b * TT + i;
        #pragma unroll
        for (int dd = 0; dd < 20; dd++)
            g_ao[(size_t)row * FEAT + h * DH + d0 + dd] = acc[dd];
    }
}

// ------------------------ score head -----------------------------------------
__global__ void score2_kernel(const float* __restrict__ W2, const float* __restrict__ b2,
                              float* __restrict__ dout, int full)
{
    int gt = blockIdx.x * blockDim.x + threadIdx.x;
    int warp = gt >> 5, lane = gt & 31;
    if (warp >= NEV) return;
    float acc = 0.f;
    for (int f = lane; f < DIMD; f += 32)
        acc += g_s1[warp * DIMD + f] * W2[f];
    #pragma unroll
    for (int o = 16; o; o >>= 1) acc += __shfl_xor_sync(0xffffffffu, acc, o);
    if (lane == 0) {
        float sc = acc + b2[0];
        float lam = fmaxf(sc, 0.f) + log1pf(expf(-fabsf(sc)));
        if (full) dout[1 + warp] = lam;
        g_loss[warp] = -logf(lam + 1e-8f);
    }
}

__global__ void loss_reduce_kernel(float* __restrict__ dout)
{
    __shared__ float s[256];
    int tid = threadIdx.x;
    float a = 0.f;
    for (int i = tid; i < NEV; i += 256) a += g_loss[i];
    s[tid] = a;
    __syncthreads();
    for (int o = 128; o; o >>= 1) {
        if (tid < o) s[tid] += s[tid + o];
        __syncthreads();
    }
    if (tid == 0) dout[0] = s[0] / (float)NEV;
}

// ------------------------ final scatter into mem / latest_time ---------------
__global__ void scatter_kernel(const int* __restrict__ subj, const int* __restrict__ obj,
                               const float* __restrict__ tim,
                               float* __restrict__ outMem, float* __restrict__ outLt)
{
    int pos = blockIdx.x * 256 + threadIdx.x;
    if (pos >= NOCC || !g_isLast[pos]) return;
    int t = pos >> 6, r = pos & 63, ph = r >> 5, b = r & 31;
    int e = ph ? obj[b * TT + t] : subj[b * TT + t];
    int ev = t * 32 + b;
    const float* src = ph ? (g_newO + ev * DIMD) : (g_newS + ev * DIMD);
    float* dst = outMem + (size_t)e * DIMD;
    for (int f = 0; f < DIMD; f++) dst[f] = src[f];
    outLt[e] = tim[b * TT + t];
}

// ------------------------ launch ---------------------------------------------
extern "C" void kernel_launch(void* const* d_in, const int* in_sizes, int n_in,
                              void* d_out, int out_size)
{
    const int*   subj = (const int*)d_in[0];
    const int*   obj  = (const int*)d_in[1];
    const int*   rel  = (const int*)d_in[2];
    const float* tim  = (const float*)d_in[3];
    const float* mem  = (const float*)d_in[4];
    const float* lt   = (const float*)d_in[5];
    const float* remb = (const float*)d_in[6];
    const float* Wh   = (const float*)d_in[7];
    const float* Whh  = (const float*)d_in[8];
    const float* Wst  = (const float*)d_in[9];
    const float* Wot  = (const float*)d_in[10];
    const float* Wq   = (const float*)d_in[11];
    const float* Wk   = (const float*)d_in[12];
    const float* Wv   = (const float*)d_in[13];
    const float* Wo   = (const float*)d_in[14];
    const float* sW1  = (const float*)d_in[15];
    const float* sb1  = (const float*)d_in[16];
    const float* sW2  = (const float*)d_in[17];
    const float* sb2  = (const float*)d_in[18];
    float* dout = (float*)d_out;
    int full = (out_size >= OUT_FULL) ? 1 : 0;

    float *p_x, *p_e, *p_q, *p_k, *p_v, *p_ao, *p_s1;
    cudaGetSymbolAddress((void**)&p_x,  g_x);
    cudaGetSymbolAddress((void**)&p_e,  g_e);
    cudaGetSymbolAddress((void**)&p_q,  g_q);
    cudaGetSymbolAddress((void**)&p_k,  g_k);
    cudaGetSymbolAddress((void**)&p_v,  g_v);
    cudaGetSymbolAddress((void**)&p_ao, g_ao);
    cudaGetSymbolAddress((void**)&p_s1, g_s1);

    cudaFuncSetAttribute(attn_kernel, cudaFuncAttributeMaxDynamicSharedMemorySize, 81920);

    // ---- phase 1: dependency analysis + waves ----
    links_kernel<<<16, 256>>>(subj, obj, tim, lt);
    depth_kernel<<<1, 256>>>();
    for (int w = 0; w < NWAVES; w++)
        wave_kernel<<<128, 256>>>(w, subj, obj, rel, mem, remb, Wh, Whh, Wst, Wot);
    assemble_x_kernel<<<(NEV * FEAT + 255) / 256, 256>>>(rel, remb);

    // ---- phase 2: attention layers ----
    for (int l = 0; l < 2; l++) {
        build_e_kernel<<<(NEV * ES + 255) / 256, 256>>>(tim);
        const float* wq = Wq + (size_t)l * INDIM * FEAT;
        const float* wk = Wk + (size_t)l * INDIM * FEAT;
        const float* wv = Wv + (size_t)l * INDIM * FEAT;
        const float* wo = Wo + (size_t)l * FEAT * FEAT;
        dim3 gq(FEAT / 64, NEV / 64);
        gemm_kernel<<<gq, 256>>>(p_e, ES, wq, FEAT, p_q, FEAT, NEV, FEAT, INDIM, 0, nullptr);
        gemm_kernel<<<gq, 256>>>(p_e, ES, wk, FEAT, p_k, FEAT, NEV, FEAT, INDIM, 0, nullptr);
        gemm_kernel<<<gq, 256>>>(p_e, ES, wv, FEAT, p_v, FEAT, NEV, FEAT, INDIM, 0, nullptr);
        attn_kernel<<<dim3(BB, NH), 256, 81920>>>();
        gemm_kernel<<<gq, 256>>>(p_ao, FEAT, wo, FEAT, p_x, FEAT, NEV, FEAT, FEAT, 1, nullptr);
    }

    // ---- score head ----
    gemm_kernel<<<dim3(DIMD / 64, NEV / 64), 256>>>(p_x, FEAT, sW1, DIMD, p_s1, DIMD,
                                                    NEV, DIMD, FEAT, 2, sb1);
    score2_kernel<<<(NEV * 32 + 255) / 256, 256>>>(sW2, sb2, dout, full);
    loss_reduce_kernel<<<1, 256>>>(dout);

    // ---- final mem / latest_time outputs ----
    if (full) {
        float* outMem = dout + 1 + NEV;
        float* outLt  = outMem + (size_t)200000 * DIMD;
        cudaMemcpyAsync(outMem, mem, (size_t)200000 * DIMD * sizeof(float),
                        cudaMemcpyDeviceToDevice, 0);
        cudaMemcpyAsync(outLt, lt, 200000 * sizeof(float),
                        cudaMemcpyDeviceToDevice, 0);
        scatter_kernel<<<16, 256>>>(subj, obj, tim, outMem, outLt);
    }
}

// round 5
// speedup vs baseline: 1.1903x; 1.1903x over previous
#include <cuda_runtime.h>
#include <cuda_bf16.h>
#include <math.h>

#define BB      32
#define TT      64
#define NEV     2048      // B*T events
#define NOCC    4096      // 2*B*T occurrences
#define DIMD    128
#define DIMC    64
#define DIML    256
#define FEAT    320
#define INDIM   449
#define ES      452       // padded e row stride
#define NH      4
#define DH      80
#define NWAVES  16
#define OUT_FULL 25802049  // 1 + 2048 + 200000*128 + 200000

// ------------------------ device scratch ------------------------------------
__device__ int   g_prevRead[NOCC];
__device__ int   g_isLast[NOCC];
__device__ int   g_depth[NEV];
__device__ int   g_order[NEV];
__device__ int   g_waveStart[NWAVES + 1];
__device__ int   g_bar[NWAVES];
__device__ float g_dts[NEV];
__device__ float g_dto[NEV];
__device__ float g_inp[NEV * FEAT];
__device__ float g_h[NEV * DIML];
__device__ float g_newS[NEV * DIMD];
__device__ float g_newO[NEV * DIMD];
__device__ float g_x[NEV * FEAT];
__device__ float g_e[NEV * ES + 64];     // +64 pad: last-tile float4 overread
__device__ float g_q[NEV * FEAT];
__device__ float g_k[NEV * FEAT];
__device__ float g_v[NEV * FEAT];
__device__ float g_ao[NEV * FEAT];
__device__ float g_s1[NEV * DIMD];
__device__ float g_loss[NEV];

__device__ __forceinline__ float sigm(float x) { return 1.f / (1.f + expf(-x)); }

// ------------------------ kernel A1: occurrence links -----------------------
// occurrence pos = t*64 + phase*32 + b   (phase 0 = subject write, 1 = object)
__global__ void links_kernel(const int* __restrict__ subj, const int* __restrict__ obj,
                             const float* __restrict__ tim, const float* __restrict__ lt)
{
    __shared__ int s_ent[NOCC];
    int tid = threadIdx.x;
    for (int p = tid; p < NOCC; p += 256) {
        int t = p >> 6, r = p & 63, ph = r >> 5, b = r & 31;
        s_ent[p] = ph ? obj[b * TT + t] : subj[b * TT + t];
    }
    __syncthreads();
    int pos = blockIdx.x * 256 + tid;
    int e = s_ent[pos];
    int t = pos >> 6, r = pos & 63, ph = r >> 5, b = r & 31;
    int stepStart = t * 64;
    int prevR = -1, later = 0;
    for (int p2 = 0; p2 < NOCC; p2++) {
        if (s_ent[p2] == e) {
            if (p2 < stepStart) prevR = p2;   // last writer before this step
            if (p2 > pos) later = 1;
        }
    }
    g_prevRead[pos] = prevR;
    g_isLast[pos] = !later;
    float ltv = (prevR < 0) ? lt[e] : tim[(prevR & 31) * TT + (prevR >> 6)];
    float dt = tim[b * TT + t] - ltv;
    int ev = t * 32 + b;
    if (ph == 0) g_dts[ev] = dt; else g_dto[ev] = dt;
}

// ------------------------ kernel A2: depths + compaction ---------------------
__global__ void depth_compact_kernel()
{
    __shared__ int s_d[NEV];
    __shared__ int s_ps[NEV];
    __shared__ int s_po[NEV];
    __shared__ int s_cnt[NWAVES];
    __shared__ int s_off[NWAVES + 1];
    int tid = threadIdx.x;
    for (int ev = tid; ev < NEV; ev += 256) {
        int t = ev >> 5, b = ev & 31;
        int ps = g_prevRead[t * 64 + b];
        int po = g_prevRead[t * 64 + 32 + b];
        s_ps[ev] = (ps < 0) ? -1 : ((ps >> 6) * 32 + (ps & 31));
        s_po[ev] = (po < 0) ? -1 : ((po >> 6) * 32 + (po & 31));
        s_d[ev] = -1;
    }
    if (tid < NWAVES) { s_cnt[tid] = 0; g_bar[tid] = 0; }
    __syncthreads();
    for (int pass = 0; pass < 32; pass++) {
        for (int ev = tid; ev < NEV; ev += 256) {
            if (s_d[ev] < 0) {
                int a = s_ps[ev], b2 = s_po[ev];
                int da = (a < 0) ? -1 : s_d[a];
                int db = (b2 < 0) ? -1 : s_d[b2];
                bool ra = (a < 0) || (da >= 0);
                bool rb = (b2 < 0) || (db >= 0);
                if (ra && rb) s_d[ev] = max(da, db) + 1;
            }
        }
        __syncthreads();
    }
    for (int ev = tid; ev < NEV; ev += 256) {
        int d = s_d[ev];
        d = (d < 0) ? 0 : ((d > NWAVES - 1) ? NWAVES - 1 : d);
        s_d[ev] = d;
        g_depth[ev] = d;
        atomicAdd(&s_cnt[d], 1);
    }
    __syncthreads();
    if (tid == 0) {
        int acc = 0;
        for (int w = 0; w < NWAVES; w++) { s_off[w] = acc; acc += s_cnt[w]; }
        s_off[NWAVES] = acc;
        for (int w = 0; w <= NWAVES; w++) g_waveStart[w] = s_off[w];
        // reuse s_cnt as running offsets
        for (int w = 0; w < NWAVES; w++) s_cnt[w] = s_off[w];
    }
    __syncthreads();
    for (int ev = tid; ev < NEV; ev += 256) {
        int pos = atomicAdd(&s_cnt[s_d[ev]], 1);
        g_order[pos] = ev;
    }
}

// ------------------------ gather wave-0 inputs -------------------------------
__global__ void gather0_kernel(const int* __restrict__ subj, const int* __restrict__ obj,
                               const int* __restrict__ rel,
                               const float* __restrict__ mem, const float* __restrict__ remb)
{
    int idx = blockIdx.x * 256 + threadIdx.x;
    if (idx >= NEV * FEAT) return;
    int row = idx / FEAT, f = idx - row * FEAT;
    if (row >= g_waveStart[1]) return;      // only depth-0 rows
    int ev = g_order[row];
    int t = ev >> 5, b = ev & 31;
    float val;
    if (f < 256) {
        int which = f >> 7, ff = f & 127;
        // depth-0 events have no in-sequence predecessor for either slot
        int ent = which ? obj[b * TT + t] : subj[b * TT + t];
        val = mem[(size_t)ent * DIMD + ff];
    } else {
        val = remb[rel[b * TT + t] * DIMC + (f - 256)];
    }
    g_inp[row * FEAT + f] = val;
}

// ------------------------ 128x64-tile fp32 GEMM body -------------------------
// epi: 0 store, 1 C += tanh(acc), 2 relu(acc+bias), 3 sigm store,
//      4 dual-sigmoid wave epilogue (bias=Wst, bias2=Wot; writes g_newS/g_newO)
__device__ __forceinline__ void gemm128_body(
    const float* __restrict__ A, int lda,
    const float* __restrict__ Bm, int ldb,
    float* __restrict__ C, int ldc,
    int K, int epi, const float* __restrict__ bias, const float* __restrict__ bias2,
    int limit)
{
    __shared__ float As[16][132];
    __shared__ float Bs[16][68];
    int tid = threadIdx.x;
    int row0 = blockIdx.y * 128;
    int col0 = blockIdx.x * 64;
    if (row0 >= limit) return;

    float acc[8][4];
    #pragma unroll
    for (int r = 0; r < 8; r++)
        #pragma unroll
        for (int c = 0; c < 4; c++) acc[r][c] = 0.f;

    int arow = tid >> 1;            // 0..127
    int ak4  = (tid & 1) * 8;       // 0 or 8
    int bk   = tid >> 4;            // 0..15
    int bn   = (tid & 15) * 4;      // 0..60
    int tx = tid & 15, ty = tid >> 4;

    for (int kt = 0; kt < K; kt += 16) {
        const float* ap = A + (size_t)(row0 + arow) * lda + kt + ak4;
        float4 av0 = *(const float4*)(ap);
        float4 av1 = *(const float4*)(ap + 4);
        As[ak4 + 0][arow] = av0.x; As[ak4 + 1][arow] = av0.y;
        As[ak4 + 2][arow] = av0.z; As[ak4 + 3][arow] = av0.w;
        As[ak4 + 4][arow] = av1.x; As[ak4 + 5][arow] = av1.y;
        As[ak4 + 6][arow] = av1.z; As[ak4 + 7][arow] = av1.w;
        int gk = kt + bk;
        float4 bv = make_float4(0.f, 0.f, 0.f, 0.f);
        if (gk < K) bv = *(const float4*)(Bm + (size_t)gk * ldb + col0 + bn);
        *(float4*)&Bs[bk][bn] = bv;
        __syncthreads();
        #pragma unroll
        for (int kk = 0; kk < 16; kk++) {
            float4 a0 = *(const float4*)&As[kk][ty * 8];
            float4 a1 = *(const float4*)&As[kk][ty * 8 + 4];
            float4 b  = *(const float4*)&Bs[kk][tx * 4];
            acc[0][0] += a0.x * b.x; acc[0][1] += a0.x * b.y; acc[0][2] += a0.x * b.z; acc[0][3] += a0.x * b.w;
            acc[1][0] += a0.y * b.x; acc[1][1] += a0.y * b.y; acc[1][2] += a0.y * b.z; acc[1][3] += a0.y * b.w;
            acc[2][0] += a0.z * b.x; acc[2][1] += a0.z * b.y; acc[2][2] += a0.z * b.z; acc[2][3] += a0.z * b.w;
            acc[3][0] += a0.w * b.x; acc[3][1] += a0.w * b.y; acc[3][2] += a0.w * b.z; acc[3][3] += a0.w * b.w;
            acc[4][0] += a1.x * b.x; acc[4][1] += a1.x * b.y; acc[4][2] += a1.x * b.z; acc[4][3] += a1.x * b.w;
            acc[5][0] += a1.y * b.x; acc[5][1] += a1.y * b.y; acc[5][2] += a1.y * b.z; acc[5][3] += a1.y * b.w;
            acc[6][0] += a1.z * b.x; acc[6][1] += a1.z * b.y; acc[6][2] += a1.z * b.z; acc[6][3] += a1.z * b.w;
            acc[7][0] += a1.w * b.x; acc[7][1] += a1.w * b.y; acc[7][2] += a1.w * b.z; acc[7][3] += a1.w * b.w;
        }
        __syncthreads();
    }
    #pragma unroll
    for (int r = 0; r < 8; r++) {
        int rr = row0 + ty * 8 + r;
        if (rr >= limit) continue;
        #pragma unroll
        for (int c = 0; c < 4; c++) {
            int cc = col0 + tx * 4 + c;
            float v = acc[r][c];
            if (epi == 0)      C[(size_t)rr * ldc + cc] = v;
            else if (epi == 1) C[(size_t)rr * ldc + cc] += tanhf(v);
            else if (epi == 2) C[(size_t)rr * ldc + cc] = fmaxf(v + bias[cc], 0.f);
            else if (epi == 3) C[(size_t)rr * ldc + cc] = sigm(v);
            else {   // epi 4: dual sigmoid, compact-row -> event scatter
                int ev = g_order[rr];
                g_newS[ev * DIMD + cc] = sigm(g_dts[ev] * bias[cc]  + v);
                g_newO[ev * DIMD + cc] = sigm(g_dto[ev] * bias2[cc] + v);
            }
        }
    }
}

__global__ void __launch_bounds__(256) gemm128_kernel(
    const float* __restrict__ A, int lda, const float* __restrict__ Bm, int ldb,
    float* __restrict__ C, int ldc, int K, int epi,
    const float* __restrict__ bias, const float* __restrict__ bias2, int useLimit)
{
    int limit = useLimit ? g_waveStart[1] : NEV;
    gemm128_body(A, lda, Bm, ldb, C, ldc, K, epi, bias, bias2, limit);
}

__global__ void __launch_bounds__(256) qkv_kernel(
    const float* __restrict__ A,
    const float* __restrict__ B0, const float* __restrict__ B1, const float* __restrict__ B2,
    float* __restrict__ C0, float* __restrict__ C1, float* __restrict__ C2)
{
    const float* Bm = (blockIdx.z == 0) ? B0 : (blockIdx.z == 1) ? B1 : B2;
    float* C = (blockIdx.z == 0) ? C0 : (blockIdx.z == 1) ? C1 : C2;
    gemm128_body(A, ES, Bm, FEAT, C, FEAT, INDIM, 0, nullptr, nullptr, NEV);
}

// ------------------------ cleanup: waves >= 1 (persistent, 16 blocks) --------
__global__ void __launch_bounds__(256) cleanup_kernel(
    const int* __restrict__ subj, const int* __restrict__ obj,
    const int* __restrict__ rel,
    const float* __restrict__ mem, const float* __restrict__ remb,
    const float* __restrict__ Wh, const float* __restrict__ Whh,
    const float* __restrict__ Wst, const float* __restrict__ Wot)
{
    __shared__ float s_inp[FEAT];
    __shared__ float s_h[DIML];
    int tid = threadIdx.x;
    for (int w = 1; w < NWAVES; w++) {
        int ws = g_waveStart[w], we = g_waveStart[w + 1];
        if (ws >= NEV) break;                 // uniform across blocks
        for (int i = ws + blockIdx.x; i < we; i += 16) {
            int ev = g_order[i];
            int t = ev >> 5, b = ev & 31;
            // gather
            for (int f = tid; f < FEAT; f += 256) {
                float val;
                if (f < 256) {
                    int which = f >> 7, ff = f & 127;
                    int pred = g_prevRead[t * 64 + which * 32 + b];
                    if (pred < 0) {
                        int ent = which ? obj[b * TT + t] : subj[b * TT + t];
                        val = mem[(size_t)ent * DIMD + ff];
                    } else {
                        int pph = (pred >> 5) & 1;
                        int pev = (pred >> 6) * 32 + (pred & 31);
                        val = pph ? g_newO[pev * DIMD + ff] : g_newS[pev * DIMD + ff];
                    }
                } else {
                    val = remb[rel[b * TT + t] * DIMC + (f - 256)];
                }
                s_inp[f] = val;
            }
            __syncthreads();
            // h = sigm(inp @ Wh)
            {
                float acc = 0.f;
                #pragma unroll 4
                for (int k = 0; k < FEAT; k++)
                    acc += s_inp[k] * Wh[(size_t)k * DIML + tid];
                s_h[tid] = sigm(acc);
            }
            __syncthreads();
            // hh + dual sigmoid
            if (tid < DIMD) {
                float acc = 0.f;
                #pragma unroll 4
                for (int k = 0; k < DIML; k++)
                    acc += s_h[k] * Whh[(size_t)k * DIMD + tid];
                g_newS[ev * DIMD + tid] = sigm(g_dts[ev] * Wst[tid] + acc);
                g_newO[ev * DIMD + tid] = sigm(g_dto[ev] * Wot[tid] + acc);
            }
            __syncthreads();
        }
        // 16-block global barrier for wave w
        __threadfence();
        __syncthreads();
        if (tid == 0) {
            atomicAdd(&g_bar[w], 1);
            while (atomicAdd(&g_bar[w], 0) < 16) { }
        }
        __syncthreads();
        __threadfence();
    }
}

// ------------------------ kernel C: assemble evt rows ------------------------
__global__ void assemble_x_kernel(const int* __restrict__ rel,
                                  const float* __restrict__ remb)
{
    int idx = blockIdx.x * 256 + threadIdx.x;
    if (idx >= NEV * FEAT) return;
    int row = idx / FEAT, f = idx - row * FEAT;  // row = b*64 + t
    int b = row >> 6, t = row & 63;
    int ev = t * 32 + b;
    float val;
    if (f < 128)      val = g_newS[ev * DIMD + f];
    else if (f < 256) val = g_newO[ev * DIMD + (f - 128)];
    else              val = remb[rel[row] * DIMC + (f - 256)];
    g_x[idx] = val;
}

// ------------------------ build e = [x | time_emb | 1 | pad] -----------------
__global__ void build_e_kernel(const float* __restrict__ tim)
{
    int idx = blockIdx.x * 256 + threadIdx.x;
    if (idx >= NEV * ES) return;
    int row = idx / ES, f = idx - row * ES;
    float val;
    if (f < FEAT) val = g_x[row * FEAT + f];
    else if (f < FEAT + DIMD) {
        int d = f - FEAT;
        float p = powf(10000.0f, (float)d);
        float nrm = (isinf(p)) ? 0.0f : (1.0f / p);
        val = sinf(tim[row] * nrm);
    } else if (f == INDIM - 1) val = 1.0f;
    else val = 0.0f;
    g_e[idx] = val;
}

// ------------------------ attention (per b,h block) --------------------------
__global__ void __launch_bounds__(256) attn_kernel()
{
    extern __shared__ float sm[];
    float* sq = sm;
    float* sk = sq + 64 * 84;
    float* sv = sk + 64 * 84;
    float* ssc = sv + 64 * 84;
    int b = blockIdx.x, h = blockIdx.y;
    int tid = threadIdx.x;
    const float scale = 0.111803398875f;  // 1/sqrt(80)

    for (int idx = tid; idx < 64 * DH; idx += 256) {
        int i = idx / DH, d = idx - i * DH;
        int row = b * TT + i, col = h * DH + d;
        sq[i * 84 + d] = g_q[(size_t)row * FEAT + col];
        sk[i * 84 + d] = g_k[(size_t)row * FEAT + col];
        sv[i * 84 + d] = g_v[(size_t)row * FEAT + col];
    }
    __syncthreads();
    {
        int i = tid >> 2, jg = tid & 3;
        float acc[16];
        #pragma unroll
        for (int jj = 0; jj < 16; jj++) acc[jj] = 0.f;
        for (int kk = 0; kk < 20; kk++) {
            float4 qv = *(const float4*)&sq[i * 84 + kk * 4];
            #pragma unroll
            for (int jj = 0; jj < 16; jj++) {
                int j = jg * 16 + jj;
                float4 kv = *(const float4*)&sk[j * 84 + kk * 4];
                acc[jj] += qv.x * kv.x + qv.y * kv.y + qv.z * kv.z + qv.w * kv.w;
            }
        }
        #pragma unroll
        for (int jj = 0; jj < 16; jj++)
            ssc[i * 68 + jg * 16 + jj] = acc[jj] * scale;
    }
    __syncthreads();
    if (tid < 64) {
        int i = tid;
        if (i == 0) {
            for (int j = 0; j < 64; j++) ssc[j] = 0.f;
        } else {
            float mx = -1e30f;
            for (int j = 0; j < i; j++) mx = fmaxf(mx, ssc[i * 68 + j]);
            float sum = 0.f;
            for (int j = 0; j < i; j++) sum += expf(ssc[i * 68 + j] - mx);
            float inv = 1.f / sum;
            for (int j = 0; j < i; j++) ssc[i * 68 + j] = expf(ssc[i * 68 + j] - mx) * inv;
            for (int j = i; j < 64; j++) ssc[i * 68 + j] = 0.f;
        }
    }
    __syncthreads();
    {
        int i = tid >> 2, dg = tid & 3, d0 = dg * 20;
        float acc[20];
        #pragma unroll
        for (int dd = 0; dd < 20; dd++) acc[dd] = 0.f;
        for (int j = 0; j < 64; j++) {
            float a = ssc[i * 68 + j];
            #pragma unroll
            for (int dd = 0; dd < 20; dd++)
                acc[dd] += a * sv[j * 84 + d0 + dd];
        }
        int row = b * TT + i;
        #pragma unroll
        for (int dd = 0; dd < 20; dd++)
            g_ao[(size_t)row * FEAT + h * DH + d0 + dd] = acc[dd];
    }
}

// ------------------------ score head -----------------------------------------
__global__ void score2_kernel(const float* __restrict__ W2, const float* __restrict__ b2,
                              float* __restrict__ dout, int full)
{
    int gt = blockIdx.x * blockDim.x + threadIdx.x;
    int warp = gt >> 5, lane = gt & 31;
    if (warp >= NEV) return;
    float acc = 0.f;
    for (int f = lane; f < DIMD; f += 32)
        acc += g_s1[warp * DIMD + f] * W2[f];
    #pragma unroll
    for (int o = 16; o; o >>= 1) acc += __shfl_xor_sync(0xffffffffu, acc, o);
    if (lane == 0) {
        float sc = acc + b2[0];
        float lam = fmaxf(sc, 0.f) + log1pf(expf(-fabsf(sc)));
        if (full) dout[1 + warp] = lam;
        g_loss[warp] = -logf(lam + 1e-8f);
    }
}

__global__ void loss_reduce_kernel(float* __restrict__ dout)
{
    __shared__ float s[256];
    int tid = threadIdx.x;
    float a = 0.f;
    for (int i = tid; i < NEV; i += 256) a += g_loss[i];
    s[tid] = a;
    __syncthreads();
    for (int o = 128; o; o >>= 1) {
        if (tid < o) s[tid] += s[tid + o];
        __syncthreads();
    }
    if (tid == 0) dout[0] = s[0] / (float)NEV;
}

// ------------------------ final scatter into mem / latest_time ---------------
__global__ void scatter_kernel(const int* __restrict__ subj, const int* __restrict__ obj,
                               const float* __restrict__ tim,
                               float* __restrict__ outMem, float* __restrict__ outLt)
{
    int pos = blockIdx.x * 256 + threadIdx.x;
    if (pos >= NOCC || !g_isLast[pos]) return;
    int t = pos >> 6, r = pos & 63, ph = r >> 5, b = r & 31;
    int e = ph ? obj[b * TT + t] : subj[b * TT + t];
    int ev = t * 32 + b;
    const float* src = ph ? (g_newO + ev * DIMD) : (g_newS + ev * DIMD);
    float* dst = outMem + (size_t)e * DIMD;
    for (int f = 0; f < DIMD; f++) dst[f] = src[f];
    outLt[e] = tim[b * TT + t];
}

// ------------------------ launch ---------------------------------------------
extern "C" void kernel_launch(void* const* d_in, const int* in_sizes, int n_in,
                              void* d_out, int out_size)
{
    const int*   subj = (const int*)d_in[0];
    const int*   obj  = (const int*)d_in[1];
    const int*   rel  = (const int*)d_in[2];
    const float* tim  = (const float*)d_in[3];
    const float* mem  = (const float*)d_in[4];
    const float* lt   = (const float*)d_in[5];
    const float* remb = (const float*)d_in[6];
    const float* Wh   = (const float*)d_in[7];
    const float* Whh  = (const float*)d_in[8];
    const float* Wst  = (const float*)d_in[9];
    const float* Wot  = (const float*)d_in[10];
    const float* Wq   = (const float*)d_in[11];
    const float* Wk   = (const float*)d_in[12];
    const float* Wv   = (const float*)d_in[13];
    const float* Wo   = (const float*)d_in[14];
    const float* sW1  = (const float*)d_in[15];
    const float* sb1  = (const float*)d_in[16];
    const float* sW2  = (const float*)d_in[17];
    const float* sb2  = (const float*)d_in[18];
    float* dout = (float*)d_out;
    int full = (out_size >= OUT_FULL) ? 1 : 0;

    float *p_x, *p_e, *p_q, *p_k, *p_v, *p_ao, *p_s1, *p_inp, *p_h;
    cudaGetSymbolAddress((void**)&p_x,   g_x);
    cudaGetSymbolAddress((void**)&p_e,   g_e);
    cudaGetSymbolAddress((void**)&p_q,   g_q);
    cudaGetSymbolAddress((void**)&p_k,   g_k);
    cudaGetSymbolAddress((void**)&p_v,   g_v);
    cudaGetSymbolAddress((void**)&p_ao,  g_ao);
    cudaGetSymbolAddress((void**)&p_s1,  g_s1);
    cudaGetSymbolAddress((void**)&p_inp, g_inp);
    cudaGetSymbolAddress((void**)&p_h,   g_h);

    cudaFuncSetAttribute(attn_kernel, cudaFuncAttributeMaxDynamicSharedMemorySize, 81920);

    // ---- phase 1 ----
    links_kernel<<<16, 256>>>(subj, obj, tim, lt);
    depth_compact_kernel<<<1, 256>>>();
    gather0_kernel<<<(NEV * FEAT + 255) / 256, 256>>>(subj, obj, rel, mem, remb);
    // h = sigm(inp @ Wh): M=2048(limited), N=256, K=320
    gemm128_kernel<<<dim3(4, 16), 256>>>(p_inp, FEAT, Wh, DIML, p_h, DIML,
                                         FEAT, 3, nullptr, nullptr, 1);
    // dual-sigmoid: M=2048(limited), N=128, K=256
    gemm128_kernel<<<dim3(2, 16), 256>>>(p_h, DIML, Whh, DIMD, p_h /*unused*/, DIMD,
                                         DIML, 4, Wst, Wot, 1);
    cleanup_kernel<<<16, 256>>>(subj, obj, rel, mem, remb, Wh, Whh, Wst, Wot);
    assemble_x_kernel<<<(NEV * FEAT + 255) / 256, 256>>>(rel, remb);

    // ---- phase 2 ----
    for (int l = 0; l < 2; l++) {
        build_e_kernel<<<(NEV * ES + 255) / 256, 256>>>(tim);
        const float* wq = Wq + (size_t)l * INDIM * FEAT;
        const float* wk = Wk + (size_t)l * INDIM * FEAT;
        const float* wv = Wv + (size_t)l * INDIM * FEAT;
        const float* wo = Wo + (size_t)l * FEAT * FEAT;
        qkv_kernel<<<dim3(5, 16, 3), 256>>>(p_e, wq, wk, wv, p_q, p_k, p_v);
        attn_kernel<<<dim3(BB, NH), 256, 81920>>>();
        gemm128_kernel<<<dim3(5, 16), 256>>>(p_ao, FEAT, wo, FEAT, p_x, FEAT,
                                             FEAT, 1, nullptr, nullptr, 0);
    }

    // ---- score head ----
    gemm128_kernel<<<dim3(2, 16), 256>>>(p_x, FEAT, sW1, DIMD, p_s1, DIMD,
                                         FEAT, 2, sb1, nullptr, 0);
    score2_kernel<<<(NEV * 32 + 255) / 256, 256>>>(sW2, sb2, dout, full);
    loss_reduce_kernel<<<1, 256>>>(dout);

    // ---- final mem / latest_time outputs ----
    if (full) {
        float* outMem = dout + 1 + NEV;
        float* outLt  = outMem + (size_t)200000 * DIMD;
        cudaMemcpyAsync(outMem, mem, (size_t)200000 * DIMD * sizeof(float),
                        cudaMemcpyDeviceToDevice, 0);
        cudaMemcpyAsync(outLt, lt, 200000 * sizeof(float),
                        cudaMemcpyDeviceToDevice, 0);
        scatter_kernel<<<16, 256>>>(subj, obj, tim, outMem, outLt);
    }
}